// round 5
// baseline (speedup 1.0000x reference)
#include <cuda_runtime.h>
#include <math.h>

// Problem constants
#define BB     256
#define TT     4096
#define NN     8
#define TWO_N  16
#define PP     144      // 2N + 2N^2
#define HH     64

// Table: latent(tt) and dlatent(tt) are functions of scalar tt in [0,1).
// 352 segments -> lerp error ~1e-6 << 1e-3 tolerance.
#define TPTS   353
#define TSEG   352

// Main kernel decomposition: 4 blocks per batch row, 256 thr, 4 samples/thr
#define GRID_MAIN 1024
#define BLK       256
#define SPT       4

__device__ float  g_table[TPTS * 32];     // per point: [0:16)=latent, [16:32)=dlatent
__device__ double g_partd[GRID_MAIN];     // data+physics partial sums
__device__ double g_parts[GRID_MAIN];     // supervised partial sums

// ---------------------------------------------------------------------------
// Kernel 1: build latent/dlatent table (accurate tanhf; trivial cost)
// ---------------------------------------------------------------------------
__global__ void table_kernel(const float* __restrict__ W1, const float* __restrict__ b1,
                             const float* __restrict__ W2, const float* __restrict__ b2) {
    __shared__ float sh[HH];
    __shared__ float sdh[HH];
    int m = blockIdx.x;
    int k = threadIdx.x;           // 64 threads
    float tt = (float)m * (1.0f / (float)TSEG);
    float w  = W1[k];
    float h  = tanhf(fmaf(tt, w, b1[k]));
    sh[k]  = h;
    sdh[k] = (1.0f - h * h) * w;   // d h / d tt
    __syncthreads();
    if (k < TWO_N) {
        float lat = b2[k];
        float dl  = 0.0f;
#pragma unroll
        for (int j = 0; j < HH; j++) {
            float w2 = W2[j * TWO_N + k];
            lat = fmaf(sh[j],  w2, lat);
            dl  = fmaf(sdh[j], w2, dl);
        }
        g_table[m * 32 + k]          = lat;
        g_table[m * 32 + TWO_N + k]  = dl;
    }
}

// ---------------------------------------------------------------------------
// Kernel 2: main loss (data + physics per (b,t) sample, plus supervised slice)
// ---------------------------------------------------------------------------
__global__ void __launch_bounds__(BLK)
main_kernel(const float* __restrict__ t_in,
            const float* __restrict__ x_target,
            const float* __restrict__ params_pred,
            const float* __restrict__ params_target,
            const float* __restrict__ ic_pred,
            const float* __restrict__ ic_target) {
    __shared__ __align__(16) float s_tab[TPTS * 32];     // 45184 B
    __shared__ __align__(16) float s_par[PP];            // g|mu|Pi|Gamma
    __shared__ double s_red[BLK / 32];
    __shared__ double s_sup[40];

    const int tid   = threadIdx.x;
    const int b     = blockIdx.x >> 2;
    const int chunk = blockIdx.x & 3;

    // Stage table + per-b params into smem
    for (int i = tid; i < TPTS * 32; i += BLK) s_tab[i] = g_table[i];
    if (tid < PP) s_par[tid] = params_pred[b * PP + tid];
    __syncthreads();

    const float* g_  = s_par;        // [8]
    const float* mu_ = s_par + 8;    // [8]
    const float* Pi_ = s_par + 16;   // [8][8]
    const float* Ga_ = s_par + 80;   // [8][8]

    float acc = 0.0f;   // data + physics squared terms (same normalizer)

#pragma unroll
    for (int it = 0; it < SPT; it++) {
        const int t = chunk * (TT / 4) + it * BLK + tid;
        const float tt = t_in[b * TT + t];

        // table lookup + lerp of 32 values
        float u  = tt * (float)TSEG;
        int   i0 = (int)u;
        i0 = min(max(i0, 0), TPTS - 2);
        const float f = u - (float)i0;

        const float4* p0 = (const float4*)(s_tab + i0 * 32);
        float L[TWO_N], D[TWO_N];
#pragma unroll
        for (int q = 0; q < 4; q++) {
            float4 a0 = p0[q], a1 = p0[q + 8];  // +8 float4 = +32 floats = next point
            L[q * 4 + 0] = fmaf(f, a1.x - a0.x, a0.x);
            L[q * 4 + 1] = fmaf(f, a1.y - a0.y, a0.y);
            L[q * 4 + 2] = fmaf(f, a1.z - a0.z, a0.z);
            L[q * 4 + 3] = fmaf(f, a1.w - a0.w, a0.w);
        }
#pragma unroll
        for (int q = 0; q < 4; q++) {
            float4 a0 = p0[4 + q], a1 = p0[12 + q];
            D[q * 4 + 0] = fmaf(f, a1.x - a0.x, a0.x);
            D[q * 4 + 1] = fmaf(f, a1.y - a0.y, a0.y);
            D[q * 4 + 2] = fmaf(f, a1.z - a0.z, a0.z);
            D[q * 4 + 3] = fmaf(f, a1.w - a0.w, a0.w);
        }

        // observables: a = L[0:8], x = relu(q - mu); tangent gated by (q-mu)>0
        float x[NN], dxt[NN];
#pragma unroll
        for (int i = 0; i < NN; i++) {
            float z   = L[NN + i] - mu_[i];
            bool  pos = z > 0.0f;
            x[i]   = pos ? z : 0.0f;
            dxt[i] = pos ? D[NN + i] : 0.0f;
        }

        // data loss: state[b,c,t] vs x_target[b,c,t]
        const float* xt = x_target + (size_t)b * TWO_N * TT + t;
#pragma unroll
        for (int c = 0; c < NN; c++) {
            float d = L[c] - xt[c * TT];
            acc = fmaf(d, d, acc);
        }
#pragma unroll
        for (int c = 0; c < NN; c++) {
            float d = x[c] - xt[(NN + c) * TT];
            acc = fmaf(d, d, acc);
        }

        // physics loss: (dstate_dt - rhs)^2
#pragma unroll
        for (int i = 0; i < NN; i++) {
            float pix = 0.0f, ga = 0.0f;
#pragma unroll
            for (int j = 0; j < NN; j++) {
                pix = fmaf(Pi_[i * NN + j], x[j], pix);
                ga  = fmaf(Ga_[i * NN + j], L[j], ga);
            }
            float rda = g_[i] + pix - L[i];
            float e1  = D[i] - rda;
            acc = fmaf(e1, e1, acc);
            float rdx = ga * (mu_[i] - x[i]);
            float e2  = dxt[i] - rdx;
            acc = fmaf(e2, e2, acc);
        }
    }

    // supervised slice: 40 elements per block covers B*160 = 40960 exactly
    if (tid < 40) {
        int idx = blockIdx.x * 40 + tid;
        int row = idx / 160;
        int col = idx - row * 160;
        float d;
        if (col < PP) d = params_pred[row * PP + col] - params_target[row * PP + col];
        else          d = ic_pred[row * TWO_N + (col - PP)] - ic_target[row * TWO_N + (col - PP)];
        s_sup[tid] = (double)d * (double)d;
    }

    // deterministic block reduction of acc
    double v = (double)acc;
#pragma unroll
    for (int off = 16; off > 0; off >>= 1)
        v += __shfl_down_sync(0xFFFFFFFFu, v, off);
    if ((tid & 31) == 0) s_red[tid >> 5] = v;
    __syncthreads();
    if (tid == 0) {
        double s = 0.0;
#pragma unroll
        for (int w = 0; w < BLK / 32; w++) s += s_red[w];
        g_partd[blockIdx.x] = s;
        double sp = 0.0;
        for (int j = 0; j < 40; j++) sp += s_sup[j];
        g_parts[blockIdx.x] = sp;
    }
}

// ---------------------------------------------------------------------------
// Kernel 3: deterministic final reduction
// ---------------------------------------------------------------------------
__global__ void finish_kernel(float* __restrict__ out) {
    __shared__ double s1[BLK];
    __shared__ double s2[BLK];
    int tid = threadIdx.x;
    double a = 0.0, c = 0.0;
    for (int i = tid; i < GRID_MAIN; i += BLK) { a += g_partd[i]; c += g_parts[i]; }
    s1[tid] = a; s2[tid] = c;
    __syncthreads();
    if (tid == 0) {
        double t1 = 0.0, t2 = 0.0;
        for (int i = 0; i < BLK; i++) { t1 += s1[i]; t2 += s2[i]; }
        // data_loss + physics_loss share normalizer B*2N*T; supervised is B*160
        double loss = t1 / (double)((size_t)BB * TWO_N * TT)
                    + t2 / (double)(BB * 160);
        out[0] = (float)loss;
    }
}

// ---------------------------------------------------------------------------
extern "C" void kernel_launch(void* const* d_in, const int* in_sizes, int n_in,
                              void* d_out, int out_size) {
    const float* t_in          = (const float*)d_in[0];  // (B,T)
    const float* x_target      = (const float*)d_in[1];  // (B,2N,T)
    const float* params_pred   = (const float*)d_in[2];  // (B,P)
    const float* params_target = (const float*)d_in[3];  // (B,P)
    const float* ic_pred       = (const float*)d_in[4];  // (B,2N)
    const float* ic_target     = (const float*)d_in[5];  // (B,2N)
    const float* W1            = (const float*)d_in[6];  // (1,H)
    const float* b1            = (const float*)d_in[7];  // (H)
    const float* W2            = (const float*)d_in[8];  // (H,2N)
    const float* b2            = (const float*)d_in[9];  // (2N)

    table_kernel<<<TPTS, HH>>>(W1, b1, W2, b2);
    main_kernel<<<GRID_MAIN, BLK>>>(t_in, x_target, params_pred, params_target,
                                    ic_pred, ic_target);
    finish_kernel<<<1, BLK>>>((float*)d_out);
}

// round 6
// speedup vs baseline: 1.2986x; 1.2986x over previous
#include <cuda_runtime.h>
#include <math.h>

// Problem constants
#define BB     256
#define TT     4096
#define NN     8
#define TWO_N  16
#define PP     144      // 2N + 2N^2
#define HH     64

// Table of latent(tt), dlatent(tt): functions of scalar tt in [0,1).
// 328 segments -> lerp error ~4e-6 << 1e-3 tolerance.
// Row stride padded to 36 floats (144B): bank = (4*i0 + off) % 32 spreads
// divergent lookups over 8 bank groups (vs stride 32 = total conflict).
#define TPTS   329
#define TSEG   328
#define ROWF   36
#define ROWF4  9        // row stride in float4

// Main kernel decomposition: 2 blocks per batch row, 256 thr, 8 samples/thr
#define GRID_MAIN 512
#define BLK       256
#define SPT       8

__device__ float  g_table[TPTS * ROWF];
__device__ double g_partd[GRID_MAIN];
__device__ double g_parts[GRID_MAIN];

// ---- packed f32x2 helpers ------------------------------------------------
__device__ __forceinline__ unsigned long long fma2u(unsigned long long a,
                                                    unsigned long long b,
                                                    unsigned long long c) {
    unsigned long long d;
    asm("fma.rn.f32x2 %0, %1, %2, %3;" : "=l"(d) : "l"(a), "l"(b), "l"(c));
    return d;
}
__device__ __forceinline__ unsigned long long pack2(float lo, float hi) {
    unsigned long long d;
    asm("mov.b64 %0, {%1, %2};" : "=l"(d) : "f"(lo), "f"(hi));
    return d;
}
union F4 { float4 v; unsigned long long u[2]; };

// ---------------------------------------------------------------------------
// Kernel 1: build latent/dlatent table (4 points per 256-thread block)
// ---------------------------------------------------------------------------
__global__ void table_kernel(const float* __restrict__ W1, const float* __restrict__ b1,
                             const float* __restrict__ W2, const float* __restrict__ b2) {
    __shared__ float sh[4][HH];
    __shared__ float sdh[4][HH];
    const int tid = threadIdx.x;
    const int sub = tid >> 6;          // point within block (0..3)
    const int k   = tid & 63;          // hidden unit
    const int m   = blockIdx.x * 4 + sub;

    float tt = (float)m * (1.0f / (float)TSEG);
    float w  = W1[k];
    float h  = tanhf(fmaf(tt, w, b1[k]));
    sh[sub][k]  = h;
    sdh[sub][k] = (1.0f - h * h) * w;
    __syncthreads();

    if (k < TWO_N && m < TPTS) {
        float lat = b2[k];
        float dl  = 0.0f;
#pragma unroll
        for (int j = 0; j < HH; j++) {
            float w2 = W2[j * TWO_N + k];
            lat = fmaf(sh[sub][j],  w2, lat);
            dl  = fmaf(sdh[sub][j], w2, dl);
        }
        g_table[m * ROWF + k]         = lat;
        g_table[m * ROWF + TWO_N + k] = dl;
    }
}

// ---------------------------------------------------------------------------
// Kernel 2: main loss (data + physics per (b,t) sample, plus supervised slice)
// ---------------------------------------------------------------------------
__global__ void __launch_bounds__(BLK)
main_kernel(const float* __restrict__ t_in,
            const float* __restrict__ x_target,
            const float* __restrict__ params_pred,
            const float* __restrict__ params_target,
            const float* __restrict__ ic_pred,
            const float* __restrict__ ic_target) {
    __shared__ __align__(16) float s_tab[TPTS * ROWF];   // 47376 B
    __shared__ __align__(16) float s_par[PP];
    __shared__ double s_red[BLK / 32];
    __shared__ double s_sup[80];

    const int tid   = threadIdx.x;
    const int b     = blockIdx.x >> 1;
    const int chunk = blockIdx.x & 1;

    for (int i = tid; i < TPTS * ROWF; i += BLK) s_tab[i] = g_table[i];
    if (tid < PP) s_par[tid] = params_pred[b * PP + tid];
    __syncthreads();

    const float* g_  = s_par;        // [8]
    const float* mu_ = s_par + 8;    // [8]
    const float* Pi_ = s_par + 16;   // [8][8]
    const float* Ga_ = s_par + 80;   // [8][8]

    double accd = 0.0;

#pragma unroll 2
    for (int it = 0; it < SPT; it++) {
        const int t = chunk * (TT / 2) + it * BLK + tid;
        const float tt = t_in[b * TT + t];

        // table index + lerp of 32 values (packed f32x2)
        float u  = tt * (float)TSEG;
        int   i0 = (int)u;
        i0 = min(max(i0, 0), TPTS - 2);
        const float f = u - (float)i0;
        const unsigned long long f2  = pack2(f, f);
        const unsigned long long mf2 = pack2(-f, -f);

        const float4* p0 = (const float4*)s_tab + i0 * ROWF4;
        float L[TWO_N], D[TWO_N];
#pragma unroll
        for (int q = 0; q < 4; q++) {
            F4 a0, a1, r;
            a0.v = p0[q]; a1.v = p0[q + ROWF4];
            r.u[0] = fma2u(f2, a1.u[0], fma2u(mf2, a0.u[0], a0.u[0]));
            r.u[1] = fma2u(f2, a1.u[1], fma2u(mf2, a0.u[1], a0.u[1]));
            L[q * 4 + 0] = r.v.x; L[q * 4 + 1] = r.v.y;
            L[q * 4 + 2] = r.v.z; L[q * 4 + 3] = r.v.w;
        }
#pragma unroll
        for (int q = 0; q < 4; q++) {
            F4 a0, a1, r;
            a0.v = p0[q + 4]; a1.v = p0[q + 4 + ROWF4];
            r.u[0] = fma2u(f2, a1.u[0], fma2u(mf2, a0.u[0], a0.u[0]));
            r.u[1] = fma2u(f2, a1.u[1], fma2u(mf2, a0.u[1], a0.u[1]));
            D[q * 4 + 0] = r.v.x; D[q * 4 + 1] = r.v.y;
            D[q * 4 + 2] = r.v.z; D[q * 4 + 3] = r.v.w;
        }

        // observables: a = L[0:8], x = relu(q - mu); tangent gated by (q-mu)>0
        float x[NN], dxt[NN];
#pragma unroll
        for (int i = 0; i < NN; i++) {
            float z   = L[NN + i] - mu_[i];
            bool  pos = z > 0.0f;
            x[i]   = pos ? z : 0.0f;
            dxt[i] = pos ? D[NN + i] : 0.0f;
        }

        float acc = 0.0f;

        // data loss
        const float* xt = x_target + (size_t)b * TWO_N * TT + t;
#pragma unroll
        for (int c = 0; c < NN; c++) {
            float d = L[c] - xt[c * TT];
            acc = fmaf(d, d, acc);
        }
#pragma unroll
        for (int c = 0; c < NN; c++) {
            float d = x[c] - xt[(NN + c) * TT];
            acc = fmaf(d, d, acc);
        }

        // physics loss
#pragma unroll
        for (int i = 0; i < NN; i++) {
            float pix = 0.0f, ga = 0.0f;
#pragma unroll
            for (int j = 0; j < NN; j++) {
                pix = fmaf(Pi_[i * NN + j], x[j], pix);
                ga  = fmaf(Ga_[i * NN + j], L[j], ga);
            }
            float e1 = D[i] - (g_[i] + pix - L[i]);
            acc = fmaf(e1, e1, acc);
            float e2 = dxt[i] - ga * (mu_[i] - x[i]);
            acc = fmaf(e2, e2, acc);
        }

        accd += (double)acc;
    }

    // supervised slice: 80 elements per block covers B*160 = 40960 exactly
    if (tid < 80) {
        int idx = blockIdx.x * 80 + tid;
        int row = idx / 160;
        int col = idx - row * 160;
        float d;
        if (col < PP) d = params_pred[row * PP + col] - params_target[row * PP + col];
        else          d = ic_pred[row * TWO_N + (col - PP)] - ic_target[row * TWO_N + (col - PP)];
        s_sup[tid] = (double)d * (double)d;
    }

    // deterministic block reduction
    double v = accd;
#pragma unroll
    for (int off = 16; off > 0; off >>= 1)
        v += __shfl_down_sync(0xFFFFFFFFu, v, off);
    if ((tid & 31) == 0) s_red[tid >> 5] = v;
    __syncthreads();
    if (tid == 0) {
        double s = 0.0;
#pragma unroll
        for (int w = 0; w < BLK / 32; w++) s += s_red[w];
        g_partd[blockIdx.x] = s;
        double sp = 0.0;
        for (int j = 0; j < 80; j++) sp += s_sup[j];
        g_parts[blockIdx.x] = sp;
    }
}

// ---------------------------------------------------------------------------
// Kernel 3: deterministic final reduction
// ---------------------------------------------------------------------------
__global__ void finish_kernel(float* __restrict__ out) {
    __shared__ double s1[BLK];
    __shared__ double s2[BLK];
    int tid = threadIdx.x;
    double a = 0.0, c = 0.0;
    for (int i = tid; i < GRID_MAIN; i += BLK) { a += g_partd[i]; c += g_parts[i]; }
    s1[tid] = a; s2[tid] = c;
    __syncthreads();
    if (tid == 0) {
        double t1 = 0.0, t2 = 0.0;
        for (int i = 0; i < BLK; i++) { t1 += s1[i]; t2 += s2[i]; }
        double loss = t1 / (double)((size_t)BB * TWO_N * TT)
                    + t2 / (double)(BB * 160);
        out[0] = (float)loss;
    }
}

// ---------------------------------------------------------------------------
extern "C" void kernel_launch(void* const* d_in, const int* in_sizes, int n_in,
                              void* d_out, int out_size) {
    const float* t_in          = (const float*)d_in[0];
    const float* x_target      = (const float*)d_in[1];
    const float* params_pred   = (const float*)d_in[2];
    const float* params_target = (const float*)d_in[3];
    const float* ic_pred       = (const float*)d_in[4];
    const float* ic_target     = (const float*)d_in[5];
    const float* W1            = (const float*)d_in[6];
    const float* b1            = (const float*)d_in[7];
    const float* W2            = (const float*)d_in[8];
    const float* b2            = (const float*)d_in[9];

    table_kernel<<<(TPTS + 3) / 4, BLK>>>(W1, b1, W2, b2);
    main_kernel<<<GRID_MAIN, BLK>>>(t_in, x_target, params_pred, params_target,
                                    ic_pred, ic_target);
    finish_kernel<<<1, BLK>>>((float*)d_out);
}